// round 13
// baseline (speedup 1.0000x reference)
#include <cuda_runtime.h>
#include <math.h>

#define NN 4
#define CC 26
#define NC 104
#define HH 512
#define WW 512
#define PH 171
#define PW 171
#define NY 169
#define NX 169
#define MTOT (NY*NX)
#define GSTR 176        // gram smem row stride (171 cols + 5 zero pad)
#define SPLIT 8
#define RPP 22          // pooled-position rows per part (last part gets 15)
#define NBLK (NC*SPLIT)
#define GTHR 192        // 6 warps = 2 position-groups x 3 triangle-thirds
#define PRB 2           // pool: output rows per block
#define RSTR 520        // pool: smem row stride (4 pad + 512 + 4)

// scratch (static device arrays; no runtime allocation)
__device__ float g_pla[NC*PH*PW];      // pooled labels
__device__ float g_ppr[NC*PH*PW];      // pooled probs
__device__ float g_part[NBLK*192];     // per-block Gram partials (171 tri + 18 sums)
__device__ double g_rmi[NC];
__device__ int    g_cnt = 0;

__device__ __forceinline__ int tri_idx(int i, int j)  // i <= j, 18x18 upper tri
{
    return i*18 - (i*(i-1))/2 + (j - i);
}

// ---------------------------------------------------------------------------
// Kernel 1: mask + sigmoid + 3x3/stride3 max-pool, smem-staged (unchanged).
// ---------------------------------------------------------------------------
__global__ __launch_bounds__(256) void pool_kernel(const float* __restrict__ cls,
                                                   const float* __restrict__ tgt,
                                                   const float* __restrict__ valid)
{
    int nc  = blockIdx.y;
    int n   = nc / CC;
    int py0 = blockIdx.x * PRB;
    int t   = threadIdx.x;

    __shared__ float sT[6*RSTR];
    __shared__ float sX[6*RSTR];

    const float* cb = cls   + (size_t)nc * HH * WW;
    const float* tb = tgt   + (size_t)nc * HH * WW;
    const float* vb = valid + (size_t)n  * HH * WW;

    const float BIG = -3.0e38f;

    for (int q = t; q < 6*128; q += 256) {
        int i = q >> 7;
        int k = q & 127;
        int r = 3*py0 - 1 + i;
        float4 T4, X4;
        if ((unsigned)r < (unsigned)HH) {
            float4 c = ((const float4*)(cb + (size_t)r*WW))[k];
            float4 g = ((const float4*)(tb + (size_t)r*WW))[k];
            float4 v = ((const float4*)(vb + (size_t)r*WW))[k];
            T4.x = g.x*v.x; T4.y = g.y*v.y; T4.z = g.z*v.z; T4.w = g.w*v.w;
            X4.x = v.x > 0.0f ? c.x : BIG;
            X4.y = v.y > 0.0f ? c.y : BIG;
            X4.z = v.z > 0.0f ? c.z : BIG;
            X4.w = v.w > 0.0f ? c.w : BIG;
        } else {
            T4.x = T4.y = T4.z = T4.w = 0.0f;
            X4.x = X4.y = X4.z = X4.w = BIG;
        }
        *(float4*)&sT[i*RSTR + 4 + 4*k] = T4;
        *(float4*)&sX[i*RSTR + 4 + 4*k] = X4;
    }
    if (t < 6) { sT[t*RSTR + 3] = 0.0f; sX[t*RSTR + 3] = BIG; }
    __syncthreads();

    for (int o = t; o < PRB*PW; o += 256) {
        int pyl = o / PW, px = o - pyl*PW;
        int py  = py0 + pyl;
        if (py >= PH) continue;
        int base = pyl*3*RSTR + 3 + 3*px;
        float mla = 0.0f, mx = BIG;
        #pragma unroll
        for (int rr = 0; rr < 3; rr++) {
            int bb = base + rr*RSTR;
            #pragma unroll
            for (int cc = 0; cc < 3; cc++) {
                mla = fmaxf(mla, sT[bb + cc]);
                mx  = fmaxf(mx,  sX[bb + cc]);
            }
        }
        float pp = 1.0f/(1.0f + __expf(-mx)) + 1e-6f;
        size_t ob = (size_t)nc * (PH*PW) + (size_t)py*PW + px;
        g_pla[ob] = mla;
        g_ppr[ob] = pp;
    }
}

// ---------------------------------------------------------------------------
// Kernel 2 (v7): direct Gram, scalar FFMA, 4-position runs.
// Antidiagonal static row split (third T owns rows {T,17-T,T+3,14-T,T+6,11-T}
// = exactly 57 entries, static loops -> full unroll + static acc indexing)
// PLUS the v5 validity guard (centers >= NX contribute nothing; smem cols
// 169/170 are real neighbor data and must not be used as centers).
// ---------------------------------------------------------------------------
template<int THIRD>
__device__ __forceinline__ void gram_third(const float* sLa, const float* sPr,
                                           int rstart, int nruns,
                                           int lane, float* red)
{
    const int R0 = THIRD, R1 = 17 - THIRD, R2 = THIRD + 3,
              R3 = 14 - THIRD, R4 = THIRD + 6, R5 = 11 - THIRD;
    float acc[57], ssum[6];
    #pragma unroll
    for (int k = 0; k < 57; k++) acc[k] = 0.0f;
    #pragma unroll
    for (int k = 0; k < 6; k++) ssum[k] = 0.0f;

    for (int r = rstart; r < nruns; r += 64) {
        int row = r / 43;
        int cb  = (r - row*43) * 4;       // image x of first center

        float A[3][8], B[3][8];
        #pragma unroll
        for (int dy = 0; dy < 3; dy++) {
            const float* la = &sLa[(row + dy)*GSTR + cb];
            const float* pr = &sPr[(row + dy)*GSTR + cb];
            float4 l0 = *(const float4*)la;
            float4 l1 = *(const float4*)(la + 4);
            float4 p0 = *(const float4*)pr;
            float4 p1 = *(const float4*)(pr + 4);
            A[dy][0]=l0.x; A[dy][1]=l0.y; A[dy][2]=l0.z; A[dy][3]=l0.w;
            A[dy][4]=l1.x; A[dy][5]=l1.y; A[dy][6]=l1.z; A[dy][7]=l1.w;
            B[dy][0]=p0.x; B[dy][1]=p0.y; B[dy][2]=p0.z; B[dy][3]=p0.w;
            B[dy][4]=p1.x; B[dy][5]=p1.y; B[dy][6]=p1.z; B[dy][7]=p1.w;
        }

        #pragma unroll
        for (int p = 0; p < 4; p++) {
            if (cb + p < NX) {          // guard: centers >= NX are invalid
                float z[18];
                #pragma unroll
                for (int dy = 0; dy < 3; dy++) {
                    z[dy*3 + 0]     = A[dy][p];
                    z[dy*3 + 1]     = A[dy][p+1];
                    z[dy*3 + 2]     = A[dy][p+2];
                    z[9 + dy*3 + 0] = B[dy][p];
                    z[9 + dy*3 + 1] = B[dy][p+1];
                    z[9 + dy*3 + 2] = B[dy][p+2];
                }
                int k = 0;
                #pragma unroll
                for (int j = R0; j < 18; j++) { acc[k] += z[R0]*z[j]; k++; }
                #pragma unroll
                for (int j = R1; j < 18; j++) { acc[k] += z[R1]*z[j]; k++; }
                #pragma unroll
                for (int j = R2; j < 18; j++) { acc[k] += z[R2]*z[j]; k++; }
                #pragma unroll
                for (int j = R3; j < 18; j++) { acc[k] += z[R3]*z[j]; k++; }
                #pragma unroll
                for (int j = R4; j < 18; j++) { acc[k] += z[R4]*z[j]; k++; }
                #pragma unroll
                for (int j = R5; j < 18; j++) { acc[k] += z[R5]*z[j]; k++; }
                #pragma unroll
                for (int s = 0; s < 6; s++) ssum[s] += z[THIRD*6 + s];
            }
        }
    }

    // warp butterfly reduce
    #pragma unroll
    for (int k = 0; k < 57; k++) {
        float v = acc[k];
        #pragma unroll
        for (int o = 16; o; o >>= 1) v += __shfl_xor_sync(0xffffffffu, v, o);
        acc[k] = v;
    }
    #pragma unroll
    for (int k = 0; k < 6; k++) {
        float v = ssum[k];
        #pragma unroll
        for (int o = 16; o; o >>= 1) v += __shfl_xor_sync(0xffffffffu, v, o);
        ssum[k] = v;
    }

    if (lane == 0) {
        int k = 0;
        #pragma unroll
        for (int j = R0; j < 18; j++) { atomicAdd(&red[tri_idx(R0, j)], acc[k]); k++; }
        #pragma unroll
        for (int j = R1; j < 18; j++) { atomicAdd(&red[tri_idx(R1, j)], acc[k]); k++; }
        #pragma unroll
        for (int j = R2; j < 18; j++) { atomicAdd(&red[tri_idx(R2, j)], acc[k]); k++; }
        #pragma unroll
        for (int j = R3; j < 18; j++) { atomicAdd(&red[tri_idx(R3, j)], acc[k]); k++; }
        #pragma unroll
        for (int j = R4; j < 18; j++) { atomicAdd(&red[tri_idx(R4, j)], acc[k]); k++; }
        #pragma unroll
        for (int j = R5; j < 18; j++) { atomicAdd(&red[tri_idx(R5, j)], acc[k]); k++; }
        #pragma unroll
        for (int s = 0; s < 6; s++)  atomicAdd(&red[171 + THIRD*6 + s], ssum[s]);
    }
}

__global__ __launch_bounds__(GTHR, 2) void gram_kernel()
{
    int b    = blockIdx.x;
    int nc   = b >> 3;
    int part = b & 7;
    int y0   = part * RPP;
    int nyp  = min(RPP, NY - y0);
    int rows = nyp + 2;

    __shared__ float sLa[(RPP+2)*GSTR];
    __shared__ float sPr[(RPP+2)*GSTR];
    __shared__ float red[192];

    const float* pla = g_pla + (size_t)nc * (PH*PW) + y0 * PW;
    const float* ppr = g_ppr + (size_t)nc * (PH*PW) + y0 * PW;
    for (int i = threadIdx.x; i < rows * GSTR; i += GTHR) {
        int rr = i / GSTR, cx = i - rr * GSTR;
        float lv = 0.0f, pv = 0.0f;
        if (cx < PW) {
            lv = pla[(size_t)rr*PW + cx];
            pv = ppr[(size_t)rr*PW + cx];
        }
        sLa[i] = lv; sPr[i] = pv;
    }
    if (threadIdx.x < 192) red[threadIdx.x] = 0.0f;
    __syncthreads();

    int warp  = threadIdx.x >> 5;
    int lane  = threadIdx.x & 31;
    int third = warp % 3;
    int group = warp / 3;            // 0 or 1
    int nruns = nyp * 43;
    int rstart = group * 32 + lane;  // stride 64

    if      (third == 0) gram_third<0>(sLa, sPr, rstart, nruns, lane, red);
    else if (third == 1) gram_third<1>(sLa, sPr, rstart, nruns, lane, red);
    else                 gram_third<2>(sLa, sPr, rstart, nruns, lane, red);

    __syncthreads();
    if (threadIdx.x < 189) g_part[(size_t)b * 192 + threadIdx.x] = red[threadIdx.x];
}

// ---------------------------------------------------------------------------
// Kernel 3: per-(n,c) 9x9 solve in fp64, block-parallel (192 threads).
// Last block (threadfence + counter) folds the final reduction. (unchanged)
// ---------------------------------------------------------------------------
__global__ __launch_bounds__(192) void solve_kernel(float* __restrict__ out)
{
    __shared__ float  red[192];
    __shared__ double A[81], La[81], W[81], Bm[81], sv[18];
    __shared__ double sm[128];
    __shared__ bool   isLast;

    int t = threadIdx.x, b = blockIdx.x;

    float a = 0.0f;
    if (t < 189) {
        #pragma unroll
        for (int p = 0; p < SPLIT; p++)
            a += g_part[(size_t)(b*SPLIT + p) * 192 + t];
    }
    red[t] = a;
    __syncthreads();
    if (t < 18) sv[t] = (double)red[171 + t];
    __syncthreads();

    const double invM = 1.0 / (double)MTOT;
    if (t < 81) {
        int d = t / 9, e = t % 9;
        int i, j;
        i = 9 + d; j = 9 + e; if (i > j) { int q = i; i = j; j = q; }
        A[t]  = (double)red[tri_idx(i, j)] - sv[9+d]*sv[9+e]*invM + (d == e ? 1e-3 : 0.0);
        i = d; j = e; if (i > j) { int q = i; i = j; j = q; }
        La[t] = (double)red[tri_idx(i, j)] - sv[d]*sv[e]*invM;
        W[t]  = (double)red[tri_idx(e, 9 + d)] - sv[e]*sv[9+d]*invM;
    }
    __syncthreads();

    if (t < 32) {
        #pragma unroll 1
        for (int j = 0; j < 9; j++) {
            if (t == 0) {
                double dd = A[j*9 + j];
                for (int k = 0; k < j; k++) dd -= A[j*9 + k]*A[j*9 + k];
                A[j*9 + j] = sqrt(fmax(dd, 1e-300));
            }
            __syncwarp();
            if (t > j && t < 9) {
                double v = A[t*9 + j];
                for (int k = 0; k < j; k++) v -= A[t*9 + k]*A[j*9 + k];
                A[t*9 + j] = v / A[j*9 + j];
            }
            __syncwarp();
        }
        #pragma unroll 1
        for (int f = 0; f < 9; f++) {
            if (t < 9) {
                double v = W[f*9 + t];
                for (int k = 0; k < f; k++) v -= A[f*9 + k]*W[k*9 + t];
                W[f*9 + t] = v / A[f*9 + f];
            }
            __syncwarp();
        }
    }
    __syncthreads();

    if (t < 81) {
        int d = t / 9, g = t % 9;
        double v = La[t];
        #pragma unroll
        for (int f = 0; f < 9; f++) v -= W[f*9 + d]*W[f*9 + g];
        Bm[t] = v + (d == g ? 1e-3 : 0.0);
    }
    __syncthreads();

    if (t < 32) {
        #pragma unroll 1
        for (int j = 0; j < 9; j++) {
            if (t == 0) {
                double dd = Bm[j*9 + j];
                for (int k = 0; k < j; k++) dd -= Bm[j*9 + k]*Bm[j*9 + k];
                Bm[j*9 + j] = sqrt(fmax(dd, 1e-300));
            }
            __syncwarp();
            if (t > j && t < 9) {
                double v = Bm[t*9 + j];
                for (int k = 0; k < j; k++) v -= Bm[t*9 + k]*Bm[j*9 + k];
                Bm[t*9 + j] = v / Bm[j*9 + j];
            }
            __syncwarp();
        }
        if (t == 0) {
            double r = 0.0;
            for (int j = 0; j < 9; j++) r += log(Bm[j*9 + j] + 1e-8);
            g_rmi[b] = r;   // == 0.5 * logdet
        }
    }
    __syncthreads();

    if (t == 0) {
        __threadfence();
        int old = atomicAdd(&g_cnt, 1);
        isLast = (old == NC - 1);
    }
    __syncthreads();
    if (isLast) {
        __threadfence();
        if (t < 128) sm[t] = (t < NC) ? g_rmi[t] : 0.0;
        __syncthreads();
        #pragma unroll
        for (int s = 64; s; s >>= 1) {
            if (t < s) sm[t] += sm[t + s];
            __syncthreads();
        }
        if (t == 0) {
            out[0] = (float)(sm[0] / 36.0);   // /4 (mean over n) /9 (HALF_D)
            g_cnt = 0;                        // reset for graph replay
        }
    }
}

// ---------------------------------------------------------------------------
extern "C" void kernel_launch(void* const* d_in, const int* in_sizes, int n_in,
                              void* d_out, int out_size)
{
    const float* cls   = (const float*)d_in[0];
    const float* tgt   = (const float*)d_in[1];
    const float* valid = (const float*)d_in[2];

    dim3 pg((PH + PRB - 1) / PRB, NC);
    pool_kernel<<<pg, 256>>>(cls, tgt, valid);
    gram_kernel<<<NBLK, GTHR>>>();
    solve_kernel<<<NC, 192>>>((float*)d_out);
}